// round 1
// baseline (speedup 1.0000x reference)
#include <cuda_runtime.h>
#include <math.h>

#define D_MODEL 1024
#define D_INNER 2048
#define D_STATE 16
#define DT_RANK 64
#define NB 2
#define LSEQ 2048
#define BL (NB*LSEQ)            /* 4096 rows total */
#define XDBL_W 96               /* dt_rank + 2*d_state */

// ---------------- scratch (device globals; no allocation allowed) ----------------
__device__ float g_xz[(size_t)BL * 2 * D_INNER];   // [4096, 4096]  in_proj output
__device__ float g_u[(size_t)BL * D_INNER];        // [4096, 2048]  conv+silu output
__device__ float g_xdbl[(size_t)BL * XDBL_W];      // [4096, 96]    x_proj output
__device__ float g_delta[(size_t)BL * D_INNER];    // [4096, 2048]  softplus(dt@W+b)
__device__ float g_y[(size_t)BL * D_INNER];        // [4096, 2048]  scan out, gated
__device__ float g_h[(size_t)BL * D_MODEL];        // [4096, 1024]  out_proj + residual

// ---------------- generic NT SGEMM: C[M,N] = A[M,K(lda)] * B[N,K]^T ----------------
// EPI: 0 = plain store, 1 = softplus(acc + bias[col]), 2 = acc + resid[row,col]
template<int EPI>
__global__ __launch_bounds__(256)
void sgemm_nt(const float* __restrict__ A, int lda,
              const float* __restrict__ Bw,
              float* __restrict__ C,
              const float* __restrict__ aux,
              int M, int N, int K)
{
    __shared__ float As[8][128];
    __shared__ float Bs[8][128];
    const int bm = blockIdx.y * 128;
    const int bn = blockIdx.x * 128;
    const int tid = threadIdx.x;
    const int tx = tid & 15;       // 0..15 -> col group
    const int ty = tid >> 4;       // 0..15 -> row group
    const int lr = tid >> 1;       // 0..127 load row
    const int lc = (tid & 1) << 2; // 0 or 4 load col (k)

    float acc[8][8];
#pragma unroll
    for (int i = 0; i < 8; i++)
#pragma unroll
        for (int j = 0; j < 8; j++) acc[i][j] = 0.f;

    const bool aval = (bm + lr) < M;
    const bool bval = (bn + lr) < N;
    const float* Aptr = A + (size_t)(bm + lr) * lda + lc;
    const float* Bptr = Bw + (size_t)(bn + lr) * K + lc;

    for (int k0 = 0; k0 < K; k0 += 8) {
        float4 av = make_float4(0.f, 0.f, 0.f, 0.f);
        float4 bv = make_float4(0.f, 0.f, 0.f, 0.f);
        if (aval) av = *(const float4*)(Aptr + k0);
        if (bval) bv = *(const float4*)(Bptr + k0);
        As[lc + 0][lr] = av.x; As[lc + 1][lr] = av.y;
        As[lc + 2][lr] = av.z; As[lc + 3][lr] = av.w;
        Bs[lc + 0][lr] = bv.x; Bs[lc + 1][lr] = bv.y;
        Bs[lc + 2][lr] = bv.z; Bs[lc + 3][lr] = bv.w;
        __syncthreads();
#pragma unroll
        for (int k = 0; k < 8; k++) {
            float a[8], b[8];
            *(float4*)&a[0] = *(const float4*)&As[k][ty * 8];
            *(float4*)&a[4] = *(const float4*)&As[k][ty * 8 + 4];
            *(float4*)&b[0] = *(const float4*)&Bs[k][tx * 8];
            *(float4*)&b[4] = *(const float4*)&Bs[k][tx * 8 + 4];
#pragma unroll
            for (int i = 0; i < 8; i++)
#pragma unroll
                for (int j = 0; j < 8; j++)
                    acc[i][j] = fmaf(a[i], b[j], acc[i][j]);
        }
        __syncthreads();
    }

#pragma unroll
    for (int i = 0; i < 8; i++) {
        int row = bm + ty * 8 + i;
        if (row >= M) continue;
#pragma unroll
        for (int j = 0; j < 8; j++) {
            int col = bn + tx * 8 + j;
            if (col >= N) continue;
            float v = acc[i][j];
            if (EPI == 1) {
                v += aux[col];
                // stable softplus = max(v,0) + log1p(exp(-|v|))
                v = fmaxf(v, 0.f) + log1pf(expf(-fabsf(v)));
            } else if (EPI == 2) {
                v += aux[(size_t)row * N + col];
            }
            C[(size_t)row * N + col] = v;
        }
    }
}

// ---------------- causal depthwise conv (width 4) + bias + SiLU ----------------
__global__ __launch_bounds__(256)
void conv_silu_kernel(const float* __restrict__ cw, const float* __restrict__ cb)
{
    int idx = blockIdx.x * blockDim.x + threadIdx.x;
    if (idx >= BL * D_INNER) return;
    int d = idx & (D_INNER - 1);
    int row = idx >> 11;           // b*LSEQ + l
    int l = row & (LSEQ - 1);

    float w0 = cw[d * 4 + 0], w1 = cw[d * 4 + 1], w2 = cw[d * 4 + 2], w3 = cw[d * 4 + 3];
    float acc = cb[d];
    // out[l] = sum_{j=0..3} in[l-3+j] * w[j]
    if (l >= 3) acc = fmaf(g_xz[(size_t)(row - 3) * (2 * D_INNER) + d], w0, acc);
    if (l >= 2) acc = fmaf(g_xz[(size_t)(row - 2) * (2 * D_INNER) + d], w1, acc);
    if (l >= 1) acc = fmaf(g_xz[(size_t)(row - 1) * (2 * D_INNER) + d], w2, acc);
    acc = fmaf(g_xz[(size_t)row * (2 * D_INNER) + d], w3, acc);
    // silu
    float s = acc / (1.f + __expf(-acc));
    g_u[(size_t)row * D_INNER + d] = s;
}

// ---------------- selective scan: one thread per (b, d) channel ----------------
__device__ __forceinline__ void loadBC(const float* xdbl_row, float* Bt, float* Ct)
{
#pragma unroll
    for (int q = 0; q < 4; q++) {
        float4 bv = *(const float4*)(xdbl_row + DT_RANK + q * 4);
        Bt[q * 4 + 0] = bv.x; Bt[q * 4 + 1] = bv.y; Bt[q * 4 + 2] = bv.z; Bt[q * 4 + 3] = bv.w;
        float4 cv = *(const float4*)(xdbl_row + DT_RANK + D_STATE + q * 4);
        Ct[q * 4 + 0] = cv.x; Ct[q * 4 + 1] = cv.y; Ct[q * 4 + 2] = cv.z; Ct[q * 4 + 3] = cv.w;
    }
}

__global__ __launch_bounds__(256)
void scan_kernel(const float* __restrict__ A_log, const float* __restrict__ Dp)
{
    int b = blockIdx.y;
    int d = blockIdx.x * blockDim.x + threadIdx.x;   // 0..2047

    float Ac[D_STATE];
#pragma unroll
    for (int n = 0; n < D_STATE; n++) Ac[n] = -expf(A_log[d * D_STATE + n]);
    const float Dd = Dp[d];

    float h[D_STATE];
#pragma unroll
    for (int n = 0; n < D_STATE; n++) h[n] = 0.f;

    const float* xdbl = g_xdbl + (size_t)b * LSEQ * XDBL_W;
    const size_t base2 = (size_t)b * LSEQ * D_INNER + d;
    const size_t base4 = (size_t)b * LSEQ * (2 * D_INNER) + D_INNER + d;

    // prefetch l = 0
    float curD = g_delta[base2];
    float curU = g_u[base2];
    float curZ = g_xz[base4];
    float Bt[D_STATE], Ct[D_STATE];
    loadBC(xdbl, Bt, Ct);

    for (int l = 0; l < LSEQ; l++) {
        float nD = 0.f, nU = 0.f, nZ = 0.f;
        float nB[D_STATE], nC[D_STATE];
        if (l + 1 < LSEQ) {
            size_t o2 = base2 + (size_t)(l + 1) * D_INNER;
            nD = g_delta[o2];
            nU = g_u[o2];
            nZ = g_xz[base4 + (size_t)(l + 1) * (2 * D_INNER)];
            loadBC(xdbl + (size_t)(l + 1) * XDBL_W, nB, nC);
        }
        // compute step l
        float du = curD * curU;
        float yt = 0.f;
#pragma unroll
        for (int n = 0; n < D_STATE; n++) {
            float dA = __expf(curD * Ac[n]);
            h[n] = fmaf(dA, h[n], du * Bt[n]);
            yt = fmaf(h[n], Ct[n], yt);
        }
        float sz = curZ / (1.f + __expf(-curZ));           // silu(z)
        g_y[base2 + (size_t)l * D_INNER] = (yt + curU * Dd) * sz;

        curD = nD; curU = nU; curZ = nZ;
#pragma unroll
        for (int n = 0; n < D_STATE; n++) { Bt[n] = nB[n]; Ct[n] = nC[n]; }
    }
}

// ---------------- LayerNorm over last dim (1024), one block per row ----------------
__global__ __launch_bounds__(256)
void ln_kernel(const float* __restrict__ lnw, const float* __restrict__ lnb,
               float* __restrict__ out)
{
    int row = blockIdx.x;
    const float* hp = g_h + (size_t)row * D_MODEL;
    int tid = threadIdx.x;

    float v[4];
    float s = 0.f, sq = 0.f;
#pragma unroll
    for (int i = 0; i < 4; i++) {
        v[i] = hp[tid + i * 256];
        s += v[i];
        sq += v[i] * v[i];
    }
#pragma unroll
    for (int off = 16; off; off >>= 1) {
        s += __shfl_xor_sync(0xffffffffu, s, off);
        sq += __shfl_xor_sync(0xffffffffu, sq, off);
    }
    __shared__ float ss[8], ssq[8];
    __shared__ float mu_s, rs_s;
    if ((tid & 31) == 0) { ss[tid >> 5] = s; ssq[tid >> 5] = sq; }
    __syncthreads();
    if (tid == 0) {
        float S = 0.f, SQ = 0.f;
#pragma unroll
        for (int i = 0; i < 8; i++) { S += ss[i]; SQ += ssq[i]; }
        float mu = S * (1.f / D_MODEL);
        float var = SQ * (1.f / D_MODEL) - mu * mu;
        mu_s = mu;
        rs_s = rsqrtf(var + 1e-5f);
    }
    __syncthreads();
    float mu = mu_s, rs = rs_s;
#pragma unroll
    for (int i = 0; i < 4; i++) {
        int c = tid + i * 256;
        out[(size_t)row * D_MODEL + c] = (v[i] - mu) * rs * lnw[c] + lnb[c];
    }
}

// ---------------- host launch ----------------
extern "C" void kernel_launch(void* const* d_in, const int* in_sizes, int n_in,
                              void* d_out, int out_size)
{
    const float* x          = (const float*)d_in[0];
    const float* in_proj_w  = (const float*)d_in[1];
    const float* conv_w     = (const float*)d_in[2];
    const float* conv_b     = (const float*)d_in[3];
    const float* x_proj_w   = (const float*)d_in[4];
    const float* dt_proj_w  = (const float*)d_in[5];
    const float* dt_proj_b  = (const float*)d_in[6];
    const float* A_log      = (const float*)d_in[7];
    const float* Dp         = (const float*)d_in[8];
    const float* out_proj_w = (const float*)d_in[9];
    const float* ln_w       = (const float*)d_in[10];
    const float* ln_b       = (const float*)d_in[11];
    float* out = (float*)d_out;

    float *p_xz, *p_u, *p_xdbl, *p_delta, *p_y, *p_h;
    cudaGetSymbolAddress((void**)&p_xz,    g_xz);
    cudaGetSymbolAddress((void**)&p_u,     g_u);
    cudaGetSymbolAddress((void**)&p_xdbl,  g_xdbl);
    cudaGetSymbolAddress((void**)&p_delta, g_delta);
    cudaGetSymbolAddress((void**)&p_y,     g_y);
    cudaGetSymbolAddress((void**)&p_h,     g_h);

    // 1) xz = x @ in_proj_w^T            [4096,4096]
    sgemm_nt<0><<<dim3(32, 32), 256>>>(x, D_MODEL, in_proj_w, p_xz, nullptr,
                                       BL, 2 * D_INNER, D_MODEL);
    // 2) u = silu(causal_conv(xi) + cb)  [4096,2048]
    conv_silu_kernel<<<(BL * D_INNER + 255) / 256, 256>>>(conv_w, conv_b);
    // 3) x_dbl = u @ x_proj_w^T          [4096,96]
    sgemm_nt<0><<<dim3(1, 32), 256>>>(p_u, D_INNER, x_proj_w, p_xdbl, nullptr,
                                      BL, XDBL_W, D_INNER);
    // 4) delta = softplus(dt @ dt_proj_w^T + b)   [4096,2048]
    sgemm_nt<1><<<dim3(16, 32), 256>>>(p_xdbl, XDBL_W, dt_proj_w, p_delta, dt_proj_b,
                                       BL, D_INNER, DT_RANK);
    // 5) selective scan + skip + gate    [4096,2048]
    scan_kernel<<<dim3(D_INNER / 256, NB), 256>>>(A_log, Dp);
    // 6) h = y @ out_proj_w^T + x        [4096,1024]
    sgemm_nt<2><<<dim3(8, 32), 256>>>(p_y, D_INNER, out_proj_w, p_h, x,
                                      BL, D_MODEL, D_INNER);
    // 7) LayerNorm -> out
    ln_kernel<<<BL, 256>>>(ln_w, ln_b, out);
}

// round 3
// speedup vs baseline: 2.7042x; 2.7042x over previous
#include <cuda_runtime.h>
#include <math.h>
#include <stdint.h>

#define D_MODEL 1024
#define D_INNER 2048
#define D_STATE 16
#define DT_RANK 64
#define NB 2
#define LSEQ 2048
#define BL (NB*LSEQ)            /* 4096 rows total */
#define XDBL_W 96               /* dt_rank + 2*d_state */

// ---------------- scratch (device globals; no allocation allowed) ----------------
__device__ float g_xz[(size_t)BL * 2 * D_INNER];   // [4096, 4096]
__device__ float g_u[(size_t)BL * D_INNER];        // [4096, 2048]
__device__ float g_xdbl[(size_t)BL * XDBL_W];      // [4096, 96]
__device__ float g_delta[(size_t)BL * D_INNER];    // [4096, 2048]
__device__ float g_y[(size_t)BL * D_INNER];        // [4096, 2048]
__device__ float g_h[(size_t)BL * D_MODEL];        // [4096, 1024]

__device__ __forceinline__ uint32_t f2tf32(float f) {
    uint32_t r; asm("cvt.rna.tf32.f32 %0, %1;" : "=r"(r) : "f"(f)); return r;
}
__device__ __forceinline__ void mma_tf32(float* d, const uint32_t* a, const uint32_t* b) {
    asm volatile(
        "mma.sync.aligned.m16n8k8.row.col.f32.tf32.tf32.f32 "
        "{%0,%1,%2,%3}, {%4,%5,%6,%7}, {%8,%9}, {%0,%1,%2,%3};"
        : "+f"(d[0]), "+f"(d[1]), "+f"(d[2]), "+f"(d[3])
        : "r"(a[0]), "r"(a[1]), "r"(a[2]), "r"(a[3]), "r"(b[0]), "r"(b[1]));
}

// ================= tf32 mma.sync GEMM: C[M,128-tile] = A[M,K] * B[N,K]^T =================
// Tiles: BM=128, BN=128, BK=32. 8 warps (4 m x 2 n), warp tile 32x64.
// EPI: 0 plain, 1 softplus(acc+aux[col]), 2 acc+aux[row*ldc+col]
#define SPITCH 36
#define ABUF (128 * SPITCH)          /* floats per A (or B) stage */
#define STAGEF (2 * ABUF)            /* floats per stage (A+B) */

template<int EPI>
__global__ __launch_bounds__(256, 1)
void gemm_mma(const float* __restrict__ A, int lda,
              const float* __restrict__ Bw, int ldb, int Nact,
              float* __restrict__ C, int ldc,
              const float* __restrict__ aux, int K)
{
    extern __shared__ float smem[];    // 2 stages * (As + Bs)
    const int tid = threadIdx.x;
    const int wid = tid >> 5;
    const int lane = tid & 31;
    const int g = lane >> 2;           // 0..7
    const int t4 = lane & 3;           // 0..3
    const int warp_m = wid >> 1;       // 0..3 -> m offset *32
    const int warp_n = wid & 1;        // 0..1 -> n offset *64
    const int bm = blockIdx.y * 128;
    const int bn = blockIdx.x * 128;

    const int ar = tid >> 1;           // load row 0..127
    const int ac = (tid & 1) << 4;     // 0 or 16

    const bool bok = (bn + ar) < Nact;
    const float* Abase = A + (size_t)(bm + ar) * lda + ac;
    const float* Bbase = Bw + (size_t)(bn + ar) * ldb + ac;

    float acc[2][8][4];
#pragma unroll
    for (int mt = 0; mt < 2; mt++)
#pragma unroll
        for (int nt = 0; nt < 8; nt++)
#pragma unroll
            for (int q = 0; q < 4; q++) acc[mt][nt][q] = 0.f;

    const int NC = K >> 5;

    float4 pa[4], pb[4];
    auto g_load = [&](int c) {
        const int k0 = c << 5;
#pragma unroll
        for (int i = 0; i < 4; i++) pa[i] = *(const float4*)(Abase + k0 + i * 4);
#pragma unroll
        for (int i = 0; i < 4; i++)
            pb[i] = bok ? *(const float4*)(Bbase + k0 + i * 4)
                        : make_float4(0.f, 0.f, 0.f, 0.f);
    };
    auto s_store = [&](int buf) {
        float* As = smem + buf * STAGEF;
        float* Bs = As + ABUF;
        uint32_t* ap = (uint32_t*)(As + ar * SPITCH + ac);
        uint32_t* bp = (uint32_t*)(Bs + ar * SPITCH + ac);
#pragma unroll
        for (int i = 0; i < 4; i++) {
            *(uint4*)(ap + i * 4) = make_uint4(f2tf32(pa[i].x), f2tf32(pa[i].y),
                                               f2tf32(pa[i].z), f2tf32(pa[i].w));
            *(uint4*)(bp + i * 4) = make_uint4(f2tf32(pb[i].x), f2tf32(pb[i].y),
                                               f2tf32(pb[i].z), f2tf32(pb[i].w));
        }
    };
    auto compute = [&](int buf) {
        const float* As = smem + buf * STAGEF;
        const float* Bs = As + ABUF;
        const float* Ab = As + (warp_m * 32 + g) * SPITCH + t4;
        const float* Bb = Bs + (warp_n * 64 + g) * SPITCH + t4;
#pragma unroll
        for (int ks = 0; ks < 4; ks++) {
            const int k0 = ks << 3;
            uint32_t afr[2][4], bfr[8][2];
#pragma unroll
            for (int mt = 0; mt < 2; mt++) {
                const float* p = Ab + mt * 16 * SPITCH + k0;
                afr[mt][0] = __float_as_uint(p[0]);
                afr[mt][1] = __float_as_uint(p[8 * SPITCH]);
                afr[mt][2] = __float_as_uint(p[4]);
                afr[mt][3] = __float_as_uint(p[8 * SPITCH + 4]);
            }
#pragma unroll
            for (int nt = 0; nt < 8; nt++) {
                const float* p = Bb + nt * 8 * SPITCH + k0;
                bfr[nt][0] = __float_as_uint(p[0]);
                bfr[nt][1] = __float_as_uint(p[4]);
            }
#pragma unroll
            for (int mt = 0; mt < 2; mt++)
#pragma unroll
                for (int nt = 0; nt < 8; nt++)
                    mma_tf32(acc[mt][nt], afr[mt], bfr[nt]);
        }
    };

    // prologue
    g_load(0);
    s_store(0);
    __syncthreads();

    for (int c = 0; c < NC; c++) {
        if (c + 1 < NC) g_load(c + 1);
        compute(c & 1);
        if (c + 1 < NC) s_store((c + 1) & 1);
        __syncthreads();
    }

    // ---------------- epilogue ----------------
#pragma unroll
    for (int mt = 0; mt < 2; mt++) {
        const int r0 = bm + warp_m * 32 + mt * 16 + g;
#pragma unroll
        for (int nt = 0; nt < 8; nt++) {
            const int col = bn + warp_n * 64 + nt * 8 + 2 * t4;
            if (col >= Nact) continue;
#pragma unroll
            for (int hrow = 0; hrow < 2; hrow++) {
                const int r = r0 + hrow * 8;
                float2 v = make_float2(acc[mt][nt][hrow * 2], acc[mt][nt][hrow * 2 + 1]);
                if (EPI == 1) {
                    float2 bs = *(const float2*)(aux + col);
                    v.x += bs.x; v.y += bs.y;
                    v.x = fmaxf(v.x, 0.f) + log1pf(expf(-fabsf(v.x)));
                    v.y = fmaxf(v.y, 0.f) + log1pf(expf(-fabsf(v.y)));
                } else if (EPI == 2) {
                    float2 rv = *(const float2*)(aux + (size_t)r * ldc + col);
                    v.x += rv.x; v.y += rv.y;
                }
                *(float2*)(C + (size_t)r * ldc + col) = v;
            }
        }
    }
}

// ---------------- causal depthwise conv (width 4) + bias + SiLU ----------------
__global__ __launch_bounds__(256)
void conv_silu_kernel(const float* __restrict__ cw, const float* __restrict__ cb)
{
    int idx = blockIdx.x * blockDim.x + threadIdx.x;
    if (idx >= BL * D_INNER) return;
    int d = idx & (D_INNER - 1);
    int row = idx >> 11;
    int l = row & (LSEQ - 1);

    float w0 = cw[d * 4 + 0], w1 = cw[d * 4 + 1], w2 = cw[d * 4 + 2], w3 = cw[d * 4 + 3];
    float acc = cb[d];
    if (l >= 3) acc = fmaf(g_xz[(size_t)(row - 3) * (2 * D_INNER) + d], w0, acc);
    if (l >= 2) acc = fmaf(g_xz[(size_t)(row - 2) * (2 * D_INNER) + d], w1, acc);
    if (l >= 1) acc = fmaf(g_xz[(size_t)(row - 1) * (2 * D_INNER) + d], w2, acc);
    acc = fmaf(g_xz[(size_t)row * (2 * D_INNER) + d], w3, acc);
    float s = acc / (1.f + __expf(-acc));
    g_u[(size_t)row * D_INNER + d] = s;
}

// ---------------- selective scan: 8 lanes per channel, 2 states/lane, time-unroll 4 ----------------
__global__ __launch_bounds__(256)
void scan_kernel(const float* __restrict__ A_log, const float* __restrict__ Dp)
{
    const int tid = threadIdx.x;
    const int ch = blockIdx.x * 32 + (tid >> 3);   // 0..4095
    const int b = ch >> 11;
    const int d = ch & (D_INNER - 1);
    const int ls = tid & 7;
    const int n0 = ls << 1;

    const float A0 = -expf(A_log[d * D_STATE + n0]);
    const float A1 = -expf(A_log[d * D_STATE + n0 + 1]);
    const float Dd = Dp[d];

    float h0 = 0.f, h1 = 0.f;
    const float* xd = g_xdbl + (size_t)b * LSEQ * XDBL_W + DT_RANK + n0;
    const size_t base2 = (size_t)b * LSEQ * D_INNER + d;
    const size_t basez = (size_t)b * LSEQ * (2 * D_INNER) + D_INNER + d;

    float cD[4], cU[4], cZ[4];
    float2 cB[4], cC[4];

    auto load_group = [&](int l, float* D_, float* U_, float* Z_, float2* B_, float2* C_) {
#pragma unroll
        for (int j = 0; j < 4; j++) {
            size_t o2 = base2 + (size_t)(l + j) * D_INNER;
            D_[j] = g_delta[o2];
            U_[j] = g_u[o2];
        }
        if (ls == 0) {
#pragma unroll
            for (int j = 0; j < 4; j++)
                Z_[j] = g_xz[basez + (size_t)(l + j) * (2 * D_INNER)];
        }
#pragma unroll
        for (int j = 0; j < 4; j++) {
            const float* xr = xd + (size_t)(l + j) * XDBL_W;
            B_[j] = *(const float2*)(xr);
            C_[j] = *(const float2*)(xr + D_STATE);
        }
    };

    load_group(0, cD, cU, cZ, cB, cC);

    for (int l0 = 0; l0 < LSEQ; l0 += 4) {
        float nD[4], nU[4], nZ[4];
        float2 nB[4], nC[4];
        const bool more = (l0 + 4) < LSEQ;
        if (more) load_group(l0 + 4, nD, nU, nZ, nB, nC);

#pragma unroll
        for (int j = 0; j < 4; j++) {
            float du = cD[j] * cU[j];
            float e0 = __expf(cD[j] * A0);
            float e1 = __expf(cD[j] * A1);
            h0 = fmaf(e0, h0, du * cB[j].x);
            h1 = fmaf(e1, h1, du * cB[j].y);
            float y = fmaf(h0, cC[j].x, h1 * cC[j].y);
            y += __shfl_xor_sync(0xffffffffu, y, 1);
            y += __shfl_xor_sync(0xffffffffu, y, 2);
            y += __shfl_xor_sync(0xffffffffu, y, 4);
            if (ls == 0) {
                float z = cZ[j];
                float sz = z / (1.f + __expf(-z));
                g_y[base2 + (size_t)(l0 + j) * D_INNER] = (y + cU[j] * Dd) * sz;
            }
        }
        if (more) {
#pragma unroll
            for (int j = 0; j < 4; j++) {
                cD[j] = nD[j]; cU[j] = nU[j]; cZ[j] = nZ[j];
                cB[j] = nB[j]; cC[j] = nC[j];
            }
        }
    }
}

// ---------------- LayerNorm over last dim (1024) ----------------
__global__ __launch_bounds__(256)
void ln_kernel(const float* __restrict__ lnw, const float* __restrict__ lnb,
               float* __restrict__ out)
{
    int row = blockIdx.x;
    const float* hp = g_h + (size_t)row * D_MODEL;
    int tid = threadIdx.x;

    float v[4];
    float s = 0.f, sq = 0.f;
#pragma unroll
    for (int i = 0; i < 4; i++) {
        v[i] = hp[tid + i * 256];
        s += v[i];
        sq += v[i] * v[i];
    }
#pragma unroll
    for (int off = 16; off; off >>= 1) {
        s += __shfl_xor_sync(0xffffffffu, s, off);
        sq += __shfl_xor_sync(0xffffffffu, sq, off);
    }
    __shared__ float ss[8], ssq[8];
    __shared__ float mu_s, rs_s;
    if ((tid & 31) == 0) { ss[tid >> 5] = s; ssq[tid >> 5] = sq; }
    __syncthreads();
    if (tid == 0) {
        float S = 0.f, SQ = 0.f;
#pragma unroll
        for (int i = 0; i < 8; i++) { S += ss[i]; SQ += ssq[i]; }
        float mu = S * (1.f / D_MODEL);
        float var = SQ * (1.f / D_MODEL) - mu * mu;
        mu_s = mu;
        rs_s = rsqrtf(var + 1e-5f);
    }
    __syncthreads();
    float mu = mu_s, rs = rs_s;
#pragma unroll
    for (int i = 0; i < 4; i++) {
        int c = tid + i * 256;
        out[(size_t)row * D_MODEL + c] = (v[i] - mu) * rs * lnw[c] + lnb[c];
    }
}

// ---------------- host launch ----------------
extern "C" void kernel_launch(void* const* d_in, const int* in_sizes, int n_in,
                              void* d_out, int out_size)
{
    const float* x          = (const float*)d_in[0];
    const float* in_proj_w  = (const float*)d_in[1];
    const float* conv_w     = (const float*)d_in[2];
    const float* conv_b     = (const float*)d_in[3];
    const float* x_proj_w   = (const float*)d_in[4];
    const float* dt_proj_w  = (const float*)d_in[5];
    const float* dt_proj_b  = (const float*)d_in[6];
    const float* A_log      = (const float*)d_in[7];
    const float* Dp         = (const float*)d_in[8];
    const float* out_proj_w = (const float*)d_in[9];
    const float* ln_w       = (const float*)d_in[10];
    const float* ln_b       = (const float*)d_in[11];
    float* out = (float*)d_out;

    float *p_xz, *p_u, *p_xdbl, *p_delta, *p_y, *p_h;
    cudaGetSymbolAddress((void**)&p_xz,    g_xz);
    cudaGetSymbolAddress((void**)&p_u,     g_u);
    cudaGetSymbolAddress((void**)&p_xdbl,  g_xdbl);
    cudaGetSymbolAddress((void**)&p_delta, g_delta);
    cudaGetSymbolAddress((void**)&p_y,     g_y);
    cudaGetSymbolAddress((void**)&p_h,     g_h);

    const int smemB = 2 * STAGEF * (int)sizeof(float);   // 73728
    cudaFuncSetAttribute(gemm_mma<0>, cudaFuncAttributeMaxDynamicSharedMemorySize, smemB);
    cudaFuncSetAttribute(gemm_mma<1>, cudaFuncAttributeMaxDynamicSharedMemorySize, smemB);
    cudaFuncSetAttribute(gemm_mma<2>, cudaFuncAttributeMaxDynamicSharedMemorySize, smemB);

    // 1) xz = x @ in_proj_w^T            [4096,4096] K=1024
    gemm_mma<0><<<dim3(32, 32), 256, smemB>>>(x, D_MODEL, in_proj_w, D_MODEL, 2 * D_INNER,
                                              p_xz, 2 * D_INNER, nullptr, D_MODEL);
    // 2) u = silu(causal_conv(xi) + cb)
    conv_silu_kernel<<<(BL * D_INNER + 255) / 256, 256>>>(conv_w, conv_b);
    // 3) x_dbl = u @ x_proj_w^T          [4096,96] K=2048
    gemm_mma<0><<<dim3(1, 32), 256, smemB>>>(p_u, D_INNER, x_proj_w, D_INNER, XDBL_W,
                                             p_xdbl, XDBL_W, nullptr, D_INNER);
    // 4) delta = softplus(dt @ dt_proj_w^T + b)   [4096,2048] K=64
    gemm_mma<1><<<dim3(16, 32), 256, smemB>>>(p_xdbl, XDBL_W, dt_proj_w, DT_RANK, D_INNER,
                                              p_delta, D_INNER, dt_proj_b, DT_RANK);
    // 5) selective scan + skip + gate
    scan_kernel<<<128, 256>>>(A_log, Dp);
    // 6) h = y @ out_proj_w^T + x        [4096,1024] K=2048
    gemm_mma<2><<<dim3(8, 32), 256, smemB>>>(p_y, D_INNER, out_proj_w, D_INNER, D_MODEL,
                                             p_h, D_MODEL, x, D_INNER);
    // 7) LayerNorm -> out
    ln_kernel<<<BL, 256>>>(ln_w, ln_b, out);
}

// round 4
// speedup vs baseline: 2.9573x; 1.0936x over previous
#include <cuda_runtime.h>
#include <math.h>
#include <stdint.h>

#define D_MODEL 1024
#define D_INNER 2048
#define D_STATE 16
#define DT_RANK 64
#define NB 2
#define LSEQ 2048
#define BL (NB*LSEQ)            /* 4096 rows total */
#define XDBL_W 96               /* dt_rank + 2*d_state */
#define SPLITK 8

// ---------------- scratch (device globals; no allocation allowed) ----------------
__device__ float g_xz[(size_t)BL * 2 * D_INNER];   // [4096, 4096]
__device__ float g_u[(size_t)BL * D_INNER];        // [4096, 2048]
__device__ float g_xdbl[(size_t)BL * XDBL_W];      // [4096, 96]
__device__ float g_delta[(size_t)BL * D_INNER];    // [4096, 2048]
__device__ float g_y[(size_t)BL * D_INNER];        // [4096, 2048]
__device__ float g_h[(size_t)BL * D_MODEL];        // [4096, 1024]
__device__ float g_part[(size_t)SPLITK * BL * XDBL_W];  // split-K partials

__device__ __forceinline__ void mma_tf32(float* d, const uint32_t* a, const uint32_t* b) {
    asm volatile(
        "mma.sync.aligned.m16n8k8.row.col.f32.tf32.tf32.f32 "
        "{%0,%1,%2,%3}, {%4,%5,%6,%7}, {%8,%9}, {%0,%1,%2,%3};"
        : "+f"(d[0]), "+f"(d[1]), "+f"(d[2]), "+f"(d[3])
        : "r"(a[0]), "r"(a[1]), "r"(a[2]), "r"(a[3]), "r"(b[0]), "r"(b[1]));
}
__device__ __forceinline__ void cp16(uint32_t dst, const void* src, bool pred) {
    int sz = pred ? 16 : 0;
    asm volatile("cp.async.cg.shared.global [%0], [%1], 16, %2;"
                 :: "r"(dst), "l"(src), "r"(sz) : "memory");
}
#define CP_COMMIT() asm volatile("cp.async.commit_group;" ::: "memory")
#define CP_WAIT(n)  asm volatile("cp.async.wait_group %0;" :: "n"(n) : "memory")

// ================= tf32 mma.sync GEMM, cp.async 4-stage: C = A[M,K] * B[N,K]^T =================
// Tiles: BM=128, BN=128, BK=32. 8 warps (4m x 2n), warp tile 32x64.
// EPI: 0 plain, 1 softplus(acc+aux[col]), 2 acc+aux[row*ldc+col]
#define SPITCH 36
#define ABUF (128 * SPITCH)            /* floats per A (or B) stage half */
#define STAGEF (2 * ABUF)              /* floats per stage */
#define STAGEB (STAGEF * 4)            /* bytes per stage */
#define NSTAGE 4

template<int EPI>
__global__ __launch_bounds__(256, 1)
void gemm_cp(const float* __restrict__ A, int lda,
             const float* __restrict__ Bw, int ldb, int Nact,
             float* __restrict__ C, int ldc,
             const float* __restrict__ aux, int K, size_t csplit)
{
    extern __shared__ float smem[];
    const int tid = threadIdx.x;
    const int wid = tid >> 5;
    const int lane = tid & 31;
    const int g = lane >> 2;
    const int t4 = lane & 3;
    const int warp_m = wid >> 1;
    const int warp_n = wid & 1;
    const int bm = blockIdx.y * 128;
    const int bn = blockIdx.x * 128;

    // split-K offsets
    const int kbase = blockIdx.z * K;
    C += (size_t)blockIdx.z * csplit;

    const int ar = tid >> 1;
    const int ac = (tid & 1) << 4;     // 0 or 16 floats

    const bool bok = (bn + ar) < Nact;
    const float* Ap = A + (size_t)(bm + ar) * lda + kbase + ac;
    const float* Bp = Bw + (size_t)(bn + ar) * ldb + kbase + ac;

    uint32_t sbase;
    asm("{ .reg .u64 t; cvta.to.shared.u64 t, %1; cvt.u32.u64 %0, t; }"
        : "=r"(sbase) : "l"(smem));
    const uint32_t dA = sbase + ((uint32_t)ar * SPITCH + ac) * 4;
    const uint32_t dB = dA + ABUF * 4;

    float acc[2][8][4];
#pragma unroll
    for (int mt = 0; mt < 2; mt++)
#pragma unroll
        for (int nt = 0; nt < 8; nt++)
#pragma unroll
            for (int q = 0; q < 4; q++) acc[mt][nt][q] = 0.f;

    const int NC = K >> 5;

    auto issue = [&](int c) {
        const uint32_t so = (uint32_t)(c & (NSTAGE - 1)) * STAGEB;
        const int k0 = c << 5;
#pragma unroll
        for (int i = 0; i < 4; i++)
            cp16(dA + so + i * 16, Ap + k0 + i * 4, true);
#pragma unroll
        for (int i = 0; i < 4; i++)
            cp16(dB + so + i * 16, Bp + k0 + i * 4, bok);
        CP_COMMIT();
    };
    auto compute = [&](int buf) {
        const float* As = smem + buf * STAGEF;
        const float* Bs = As + ABUF;
        const float* Ab = As + (warp_m * 32 + g) * SPITCH + t4;
        const float* Bb = Bs + (warp_n * 64 + g) * SPITCH + t4;
#pragma unroll
        for (int ks = 0; ks < 4; ks++) {
            const int k0 = ks << 3;
            uint32_t afr[2][4], bfr[8][2];
#pragma unroll
            for (int mt = 0; mt < 2; mt++) {
                const float* p = Ab + mt * 16 * SPITCH + k0;
                afr[mt][0] = __float_as_uint(p[0]);
                afr[mt][1] = __float_as_uint(p[8 * SPITCH]);
                afr[mt][2] = __float_as_uint(p[4]);
                afr[mt][3] = __float_as_uint(p[8 * SPITCH + 4]);
            }
#pragma unroll
            for (int nt = 0; nt < 8; nt++) {
                const float* p = Bb + nt * 8 * SPITCH + k0;
                bfr[nt][0] = __float_as_uint(p[0]);
                bfr[nt][1] = __float_as_uint(p[4]);
            }
#pragma unroll
            for (int mt = 0; mt < 2; mt++)
#pragma unroll
                for (int nt = 0; nt < 8; nt++)
                    mma_tf32(acc[mt][nt], afr[mt], bfr[nt]);
        }
    };

    // prologue: up to 3 chunks in flight
    const int npre = (NC < 3) ? NC : 3;
    for (int c = 0; c < npre; c++) issue(c);

    for (int c = 0; c < NC; c++) {
        const int rem = NC - 1 - c;
        if (rem >= 2)      CP_WAIT(2);
        else if (rem == 1) CP_WAIT(1);
        else               CP_WAIT(0);
        __syncthreads();
        if (c + 3 < NC) issue(c + 3);
        compute(c & (NSTAGE - 1));
    }

    // ---------------- epilogue ----------------
#pragma unroll
    for (int mt = 0; mt < 2; mt++) {
        const int r0 = bm + warp_m * 32 + mt * 16 + g;
#pragma unroll
        for (int nt = 0; nt < 8; nt++) {
            const int col = bn + warp_n * 64 + nt * 8 + 2 * t4;
            if (col >= Nact) continue;
#pragma unroll
            for (int hrow = 0; hrow < 2; hrow++) {
                const int r = r0 + hrow * 8;
                float2 v = make_float2(acc[mt][nt][hrow * 2], acc[mt][nt][hrow * 2 + 1]);
                if (EPI == 1) {
                    float2 bs = *(const float2*)(aux + col);
                    v.x += bs.x; v.y += bs.y;
                    v.x = fmaxf(v.x, 0.f) + log1pf(expf(-fabsf(v.x)));
                    v.y = fmaxf(v.y, 0.f) + log1pf(expf(-fabsf(v.y)));
                } else if (EPI == 2) {
                    float2 rv = *(const float2*)(aux + (size_t)r * ldc + col);
                    v.x += rv.x; v.y += rv.y;
                }
                *(float2*)(C + (size_t)r * ldc + col) = v;
            }
        }
    }
}

// ---------------- split-K reduce: g_xdbl = sum_s g_part[s] ----------------
__global__ __launch_bounds__(256)
void reduce_split_kernel()
{
    int idx = blockIdx.x * blockDim.x + threadIdx.x;
    if (idx >= BL * XDBL_W) return;
    float s = 0.f;
#pragma unroll
    for (int k = 0; k < SPLITK; k++)
        s += g_part[(size_t)k * BL * XDBL_W + idx];
    g_xdbl[idx] = s;
}

// ---------------- causal depthwise conv (width 4) + bias + SiLU ----------------
__global__ __launch_bounds__(256)
void conv_silu_kernel(const float* __restrict__ cw, const float* __restrict__ cb)
{
    int idx = blockIdx.x * blockDim.x + threadIdx.x;
    if (idx >= BL * D_INNER) return;
    int d = idx & (D_INNER - 1);
    int row = idx >> 11;
    int l = row & (LSEQ - 1);

    float w0 = cw[d * 4 + 0], w1 = cw[d * 4 + 1], w2 = cw[d * 4 + 2], w3 = cw[d * 4 + 3];
    float acc = cb[d];
    if (l >= 3) acc = fmaf(g_xz[(size_t)(row - 3) * (2 * D_INNER) + d], w0, acc);
    if (l >= 2) acc = fmaf(g_xz[(size_t)(row - 2) * (2 * D_INNER) + d], w1, acc);
    if (l >= 1) acc = fmaf(g_xz[(size_t)(row - 1) * (2 * D_INNER) + d], w2, acc);
    acc = fmaf(g_xz[(size_t)row * (2 * D_INNER) + d], w3, acc);
    float s = acc / (1.f + __expf(-acc));
    g_u[(size_t)row * D_INNER + d] = s;
}

// ---------------- selective scan: 8 lanes per channel, 2 states/lane, time-unroll 4 ----------------
__global__ __launch_bounds__(256)
void scan_kernel(const float* __restrict__ A_log, const float* __restrict__ Dp)
{
    const int tid = threadIdx.x;
    const int ch = blockIdx.x * 32 + (tid >> 3);   // 0..4095
    const int b = ch >> 11;
    const int d = ch & (D_INNER - 1);
    const int ls = tid & 7;
    const int n0 = ls << 1;

    const float A0 = -expf(A_log[d * D_STATE + n0]);
    const float A1 = -expf(A_log[d * D_STATE + n0 + 1]);
    const float Dd = Dp[d];

    float h0 = 0.f, h1 = 0.f;
    const float* xd = g_xdbl + (size_t)b * LSEQ * XDBL_W + DT_RANK + n0;
    const size_t base2 = (size_t)b * LSEQ * D_INNER + d;
    const size_t basez = (size_t)b * LSEQ * (2 * D_INNER) + D_INNER + d;

    float cD[4], cU[4], cZ[4];
    float2 cB[4], cC[4];

    auto load_group = [&](int l, float* D_, float* U_, float* Z_, float2* B_, float2* C_) {
#pragma unroll
        for (int j = 0; j < 4; j++) {
            size_t o2 = base2 + (size_t)(l + j) * D_INNER;
            D_[j] = g_delta[o2];
            U_[j] = g_u[o2];
        }
        if (ls == 0) {
#pragma unroll
            for (int j = 0; j < 4; j++)
                Z_[j] = g_xz[basez + (size_t)(l + j) * (2 * D_INNER)];
        }
#pragma unroll
        for (int j = 0; j < 4; j++) {
            const float* xr = xd + (size_t)(l + j) * XDBL_W;
            B_[j] = *(const float2*)(xr);
            C_[j] = *(const float2*)(xr + D_STATE);
        }
    };

    load_group(0, cD, cU, cZ, cB, cC);

    for (int l0 = 0; l0 < LSEQ; l0 += 4) {
        float nD[4], nU[4], nZ[4];
        float2 nB[4], nC[4];
        const bool more = (l0 + 4) < LSEQ;
        if (more) load_group(l0 + 4, nD, nU, nZ, nB, nC);

#pragma unroll
        for (int j = 0; j < 4; j++) {
            float du = cD[j] * cU[j];
            float e0 = __expf(cD[j] * A0);
            float e1 = __expf(cD[j] * A1);
            h0 = fmaf(e0, h0, du * cB[j].x);
            h1 = fmaf(e1, h1, du * cB[j].y);
            float y = fmaf(h0, cC[j].x, h1 * cC[j].y);
            y += __shfl_xor_sync(0xffffffffu, y, 1);
            y += __shfl_xor_sync(0xffffffffu, y, 2);
            y += __shfl_xor_sync(0xffffffffu, y, 4);
            if (ls == 0) {
                float z = cZ[j];
                float sz = z / (1.f + __expf(-z));
                g_y[base2 + (size_t)(l0 + j) * D_INNER] = (y + cU[j] * Dd) * sz;
            }
        }
        if (more) {
#pragma unroll
            for (int j = 0; j < 4; j++) {
                cD[j] = nD[j]; cU[j] = nU[j]; cZ[j] = nZ[j];
                cB[j] = nB[j]; cC[j] = nC[j];
            }
        }
    }
}

// ---------------- LayerNorm over last dim (1024) ----------------
__global__ __launch_bounds__(256)
void ln_kernel(const float* __restrict__ lnw, const float* __restrict__ lnb,
               float* __restrict__ out)
{
    int row = blockIdx.x;
    const float* hp = g_h + (size_t)row * D_MODEL;
    int tid = threadIdx.x;

    float v[4];
    float s = 0.f, sq = 0.f;
#pragma unroll
    for (int i = 0; i < 4; i++) {
        v[i] = hp[tid + i * 256];
        s += v[i];
        sq += v[i] * v[i];
    }
#pragma unroll
    for (int off = 16; off; off >>= 1) {
        s += __shfl_xor_sync(0xffffffffu, s, off);
        sq += __shfl_xor_sync(0xffffffffu, sq, off);
    }
    __shared__ float ss[8], ssq[8];
    __shared__ float mu_s, rs_s;
    if ((tid & 31) == 0) { ss[tid >> 5] = s; ssq[tid >> 5] = sq; }
    __syncthreads();
    if (tid == 0) {
        float S = 0.f, SQ = 0.f;
#pragma unroll
        for (int i = 0; i < 8; i++) { S += ss[i]; SQ += ssq[i]; }
        float mu = S * (1.f / D_MODEL);
        float var = SQ * (1.f / D_MODEL) - mu * mu;
        mu_s = mu;
        rs_s = rsqrtf(var + 1e-5f);
    }
    __syncthreads();
    float mu = mu_s, rs = rs_s;
#pragma unroll
    for (int i = 0; i < 4; i++) {
        int c = tid + i * 256;
        out[(size_t)row * D_MODEL + c] = (v[i] - mu) * rs * lnw[c] + lnb[c];
    }
}

// ---------------- host launch ----------------
extern "C" void kernel_launch(void* const* d_in, const int* in_sizes, int n_in,
                              void* d_out, int out_size)
{
    const float* x          = (const float*)d_in[0];
    const float* in_proj_w  = (const float*)d_in[1];
    const float* conv_w     = (const float*)d_in[2];
    const float* conv_b     = (const float*)d_in[3];
    const float* x_proj_w   = (const float*)d_in[4];
    const float* dt_proj_w  = (const float*)d_in[5];
    const float* dt_proj_b  = (const float*)d_in[6];
    const float* A_log      = (const float*)d_in[7];
    const float* Dp         = (const float*)d_in[8];
    const float* out_proj_w = (const float*)d_in[9];
    const float* ln_w       = (const float*)d_in[10];
    const float* ln_b       = (const float*)d_in[11];
    float* out = (float*)d_out;

    float *p_xz, *p_u, *p_delta, *p_y, *p_h, *p_part;
    cudaGetSymbolAddress((void**)&p_xz,    g_xz);
    cudaGetSymbolAddress((void**)&p_u,     g_u);
    cudaGetSymbolAddress((void**)&p_delta, g_delta);
    cudaGetSymbolAddress((void**)&p_y,     g_y);
    cudaGetSymbolAddress((void**)&p_h,     g_h);
    cudaGetSymbolAddress((void**)&p_part,  g_part);
    float* p_xdbl;
    cudaGetSymbolAddress((void**)&p_xdbl,  g_xdbl);

    const int smemB = NSTAGE * STAGEB;   // 4 * 36864 = 147456
    cudaFuncSetAttribute(gemm_cp<0>, cudaFuncAttributeMaxDynamicSharedMemorySize, smemB);
    cudaFuncSetAttribute(gemm_cp<1>, cudaFuncAttributeMaxDynamicSharedMemorySize, smemB);
    cudaFuncSetAttribute(gemm_cp<2>, cudaFuncAttributeMaxDynamicSharedMemorySize, smemB);

    // 1) xz = x @ in_proj_w^T            [4096,4096] K=1024
    gemm_cp<0><<<dim3(32, 32), 256, smemB>>>(x, D_MODEL, in_proj_w, D_MODEL, 2 * D_INNER,
                                             p_xz, 2 * D_INNER, nullptr, D_MODEL, 0);
    // 2) u = silu(causal_conv(xi) + cb)
    conv_silu_kernel<<<(BL * D_INNER + 255) / 256, 256>>>(conv_w, conv_b);
    // 3) x_dbl = u @ x_proj_w^T  [4096,96], split-K x8 (K=256 each) + reduce
    gemm_cp<0><<<dim3(1, 32, SPLITK), 256, smemB>>>(p_u, D_INNER, x_proj_w, D_INNER, XDBL_W,
                                                    p_part, XDBL_W, nullptr,
                                                    D_INNER / SPLITK, (size_t)BL * XDBL_W);
    reduce_split_kernel<<<(BL * XDBL_W + 255) / 256, 256>>>();
    // 4) delta = softplus(dt @ dt_proj_w^T + b)   [4096,2048] K=64
    gemm_cp<1><<<dim3(16, 32), 256, smemB>>>(p_xdbl, XDBL_W, dt_proj_w, DT_RANK, D_INNER,
                                             p_delta, D_INNER, dt_proj_b, DT_RANK, 0);
    // 5) selective scan + skip + gate
    scan_kernel<<<128, 256>>>(A_log, Dp);
    // 6) h = y @ out_proj_w^T + x        [4096,1024] K=2048
    gemm_cp<2><<<dim3(8, 32), 256, smemB>>>(p_y, D_INNER, out_proj_w, D_INNER, D_MODEL,
                                            p_h, D_MODEL, x, D_INNER, 0);
    // 7) LayerNorm -> out
    ln_kernel<<<BL, 256>>>(ln_w, ln_b, out);
}